// round 12
// baseline (speedup 1.0000x reference)
#include <cuda_runtime.h>
#include <stdint.h>

#define N_RAYS    32768
#define N_OBJ     16
#define N_SAMPLES 32
#define N_BASE    64
#define N_ZOBJ    (N_OBJ * N_SAMPLES)            // 512
#define TOTAL     (N_BASE + N_ZOBJ)              // 576
#define MISS      1e10f

// ---- per-object transform constants ----
__device__ float g_R [N_OBJ][9];
__device__ float g_T [N_OBJ][3];
__device__ float g_iR[N_OBJ][9];
__device__ float g_iT[N_OBJ][3];

// XLA-GPU lowers x/sqrt(s) -> x * rsqrt(s) with rsqrt.approx.f32.
__device__ __forceinline__ float rsqrt_approx(float x) {
    float r;
    asm("rsqrt.approx.f32 %0, %1;" : "=f"(r) : "f"(x));
    return r;
}

// ---------------------------------------------------------------------------
// Kernel 0: pt_mat = trafos @ scales; inverse exact in fp64, rounded to fp32.
// (bit-identical to Round 7 — arithmetic locked)
// ---------------------------------------------------------------------------
__global__ void precompute_kernel(const float* __restrict__ trafos,
                                  const float* __restrict__ scales) {
    int m = threadIdx.x;
    if (m >= N_OBJ) return;
    const float* A = trafos + m * 16;
    const float* B = scales + m * 16;
    float s0 = B[0], s1 = B[5], s2 = B[10];
    float R[9], T[3];
    #pragma unroll
    for (int i = 0; i < 3; i++) {
        R[i * 3 + 0] = __fmul_rn(A[i * 4 + 0], s0);
        R[i * 3 + 1] = __fmul_rn(A[i * 4 + 1], s1);
        R[i * 3 + 2] = __fmul_rn(A[i * 4 + 2], s2);
    }
    T[0] = __fmul_rn(A[12], s0);
    T[1] = __fmul_rn(A[13], s1);
    T[2] = __fmul_rn(A[14], s2);

    double a = R[0], b = R[1], c = R[2];
    double d = R[3], e = R[4], f = R[5];
    double g = R[6], h = R[7], i = R[8];
    double A0 = e * i - f * h, B0 = -(d * i - f * g), C0 = d * h - e * g;
    double D0 = -(b * i - c * h), E0 = a * i - c * g, F0 = -(a * h - b * g);
    double G0 = b * f - c * e, H0 = -(a * f - c * d), I0 = a * e - b * d;
    double det = a * A0 + b * B0 + c * C0;
    double id = 1.0 / det;
    double iR[9] = { A0 * id, D0 * id, G0 * id,
                     B0 * id, E0 * id, H0 * id,
                     C0 * id, F0 * id, I0 * id };
    double iT[3];
    #pragma unroll
    for (int j = 0; j < 3; j++)
        iT[j] = -((double)T[0] * iR[0 + j] + (double)T[1] * iR[3 + j]
                  + (double)T[2] * iR[6 + j]);

    #pragma unroll
    for (int k = 0; k < 9; k++) { g_R[m][k] = R[k]; g_iR[m][k] = (float)iR[k]; }
    #pragma unroll
    for (int k = 0; k < 3; k++) { g_T[m][k] = T[k]; g_iT[m][k] = (float)iT[k]; }
}

__device__ __forceinline__ float dot3_fma(float x0, float x1, float x2,
                                          float m0, float m1, float m2) {
    return fmaf(x2, m2, fmaf(x1, m1, __fmul_rn(x0, m0)));
}

__device__ __forceinline__ unsigned float_to_ord(float f) {
    unsigned u = __float_as_uint(f);
    return (u & 0x80000000u) ? ~u : (u | 0x80000000u);
}
__device__ __forceinline__ float ord_to_float(unsigned u) {
    return (u & 0x80000000u) ? __uint_as_float(u ^ 0x80000000u)
                             : __uint_as_float(~u);
}

// Branchless counts over power-of-two-length sorted arrays (32-bit keys).
template <int L>
__device__ __forceinline__ int cnt_lt32(const unsigned* __restrict__ a, unsigned u) {
    int base = 0;
    #pragma unroll
    for (int half = L >> 1; half > 0; half >>= 1)
        if (a[base + half - 1] < u) base += half;
    return base + ((a[base] < u) ? 1 : 0);
}
template <int L>
__device__ __forceinline__ int cnt_le32(const unsigned* __restrict__ a, unsigned u) {
    int base = 0;
    #pragma unroll
    for (int half = L >> 1; half > 0; half >>= 1)
        if (a[base + half - 1] <= u) base += half;
    return base + ((a[base] <= u) ? 1 : 0);
}

// One merge round: runs of length 2^LOG2H -> 2^(LOG2H+1). Key stays in a
// register; only the 4-byte ord moves through smem. Left run uses cnt_lt of
// right (left's original indices are smaller), right uses cnt_le.
template <int LOG2H>
__device__ __forceinline__ int merge_round(const unsigned* __restrict__ src,
                                           unsigned* __restrict__ dst,
                                           int gpos, unsigned ord) {
    constexpr int HALF = 1 << LOG2H;
    int rank = gpos & (HALF - 1);
    int run  = gpos >> LOG2H;
    const unsigned* other = src + ((run ^ 1) << LOG2H);
    int cnt = (run & 1) ? cnt_le32<HALF>(other, ord)
                        : cnt_lt32<HALF>(other, ord);
    int np = ((run >> 1) << (LOG2H + 1)) + rank + cnt;
    dst[np] = ord;
    return np;
}

// ---------------------------------------------------------------------------
// Fused kernel: one block (576 threads) per ray.
// Phase A: warp 0 lanes 0-15 compute warp-uniform per-object geometry once.
// Phase B: object warps do only per-sample work. Sort: 32-bit per-warp
// bitonic + payload-free merge tree. All fp sequences identical to R11.
// ---------------------------------------------------------------------------
__global__ void __launch_bounds__(TOTAL, 3)
fused_kernel(const float* __restrict__ origins,
             const float* __restrict__ directions,
             const float* __restrict__ lengths,
             float* __restrict__ out_len,
             float* __restrict__ out_node,
             float* __restrict__ out_mask,
             float* __restrict__ out_pts,
             float* __restrict__ out_dirs) {
    __shared__ unsigned           s_objA[N_ZOBJ];
    __shared__ unsigned           s_objB[N_ZOBJ];
    __shared__ unsigned           s_base[N_BASE];
    __shared__ float              s_geo [N_OBJ][8];   // oo0..2, do0..2, tin, tmax
    __shared__ unsigned char      s_hit [N_OBJ];
    __shared__ unsigned long long s_pack[TOTAL];

    const int n    = blockIdx.x;
    const int tid  = threadIdx.x;
    const int wid  = tid >> 5;
    const int lane = tid & 31;

    unsigned myord = 0;
    int gpos = 0;
    int mynode = -1;

    // ---- phase A: base loads + per-object slab precompute ----
    if (tid < N_BASE) {
        float f = __ldg(lengths + (size_t)n * N_BASE + tid);
        myord = float_to_ord(f);
        s_base[tid] = myord;
    }
    if (wid == 0 && lane < N_OBJ) {
        const int m = lane;
        float ox = __ldg(origins + 3 * n + 0);
        float oy = __ldg(origins + 3 * n + 1);
        float oz = __ldg(origins + 3 * n + 2);
        float dx = __ldg(directions + 3 * n + 0);
        float dy = __ldg(directions + 3 * n + 1);
        float dz = __ldg(directions + 3 * n + 2);

        float dss = __fadd_rn(__fadd_rn(__fmul_rn(dx, dx), __fmul_rn(dy, dy)),
                              __fmul_rn(dz, dz));
        float drs = rsqrt_approx(dss);
        float dwx = __fmul_rn(dx, drs), dwy = __fmul_rn(dy, drs), dwz = __fmul_rn(dz, drs);

        const float* R = g_R[m];
        const float* T = g_T[m];
        float oo0 = __fadd_rn(dot3_fma(ox, oy, oz, R[0], R[3], R[6]), T[0]);
        float oo1 = __fadd_rn(dot3_fma(ox, oy, oz, R[1], R[4], R[7]), T[1]);
        float oo2 = __fadd_rn(dot3_fma(ox, oy, oz, R[2], R[5], R[8]), T[2]);
        float dr0 = dot3_fma(dwx, dwy, dwz, R[0], R[3], R[6]);
        float dr1 = dot3_fma(dwx, dwy, dwz, R[1], R[4], R[7]);
        float dr2 = dot3_fma(dwx, dwy, dwz, R[2], R[5], R[8]);
        float oss = __fadd_rn(__fadd_rn(__fmul_rn(dr0, dr0), __fmul_rn(dr1, dr1)),
                              __fmul_rn(dr2, dr2));
        float ors = rsqrt_approx(oss);
        float do0 = __fmul_rn(dr0, ors), do1 = __fmul_rn(dr1, ors), do2 = __fmul_rn(dr2, ors);

        float i0 = __fdiv_rn(1.f, do0), i1 = __fdiv_rn(1.f, do1), i2 = __fdiv_rn(1.f, do2);
        float t0x = __fmul_rn(__fsub_rn(-1.f, oo0), i0), t1x = __fmul_rn(__fsub_rn(1.f, oo0), i0);
        float t0y = __fmul_rn(__fsub_rn(-1.f, oo1), i1), t1y = __fmul_rn(__fsub_rn(1.f, oo1), i1);
        float t0z = __fmul_rn(__fsub_rn(-1.f, oo2), i2), t1z = __fmul_rn(__fsub_rn(1.f, oo2), i2);
        float tmin = fmaxf(fmaxf(fminf(t0x, t1x), fminf(t0y, t1y)), fminf(t0z, t1z));
        float tmax = fminf(fminf(fmaxf(t0x, t1x), fmaxf(t0y, t1y)), fmaxf(t0z, t1z));
        bool hit = (tmax > tmin) && (tmax > 0.f);
        float tin = fmaxf(tmin, 0.f);

        s_geo[m][0] = oo0; s_geo[m][1] = oo1; s_geo[m][2] = oo2;
        s_geo[m][3] = do0; s_geo[m][4] = do1; s_geo[m][5] = do2;
        s_geo[m][6] = tin; s_geo[m][7] = tmax;
        s_hit[m] = hit ? 1 : 0;
    }
    __syncthreads();

    // ---- phase B: per-sample work (object warps) ----
    if (wid >= 2) {
        const int m = wid - 2;

        float ox = __ldg(origins + 3 * n + 0);
        float oy = __ldg(origins + 3 * n + 1);
        float oz = __ldg(origins + 3 * n + 2);
        float dx = __ldg(directions + 3 * n + 0);
        float dy = __ldg(directions + 3 * n + 1);
        float dz = __ldg(directions + 3 * n + 2);
        float dss = __fadd_rn(__fadd_rn(__fmul_rn(dx, dx), __fmul_rn(dy, dy)),
                              __fmul_rn(dz, dz));
        float drs = rsqrt_approx(dss);
        float dwx = __fmul_rn(dx, drs), dwy = __fmul_rn(dy, drs), dwz = __fmul_rn(dz, drs);

        float oo0 = s_geo[m][0], oo1 = s_geo[m][1], oo2 = s_geo[m][2];
        float do0 = s_geo[m][3], do1 = s_geo[m][4], do2 = s_geo[m][5];
        float tin = s_geo[m][6], tmax = s_geo[m][7];
        bool hit = s_hit[m] != 0;
        float hf = hit ? 1.f : 0.f;
        mynode = hit ? m : -1;

        float lin = __fdiv_rn((float)lane, 31.0f);
        float zo  = __fadd_rn(tin, __fmul_rn(__fsub_rn(tmax, tin), lin));
        float p0 = __fadd_rn(oo0, __fmul_rn(do0, zo));
        float p1 = __fadd_rn(oo1, __fmul_rn(do1, zo));
        float p2 = __fadd_rn(oo2, __fmul_rn(do2, zo));

        size_t base = ((size_t)(m * N_RAYS + n) * N_SAMPLES + lane) * 3;
        out_pts [base + 0] = __fmul_rn(p0, hf);
        out_pts [base + 1] = __fmul_rn(p1, hf);
        out_pts [base + 2] = __fmul_rn(p2, hf);
        out_dirs[base + 0] = __fmul_rn(do0, hf);
        out_dirs[base + 1] = __fmul_rn(do1, hf);
        out_dirs[base + 2] = __fmul_rn(do2, hf);

        const float* iR = g_iR[m];
        const float* iT = g_iT[m];
        float w0 = __fadd_rn(dot3_fma(p0, p1, p2, iR[0], iR[3], iR[6]), iT[0]);
        float w1 = __fadd_rn(dot3_fma(p0, p1, p2, iR[1], iR[4], iR[7]), iT[1]);
        float w2 = __fadd_rn(dot3_fma(p0, p1, p2, iR[2], iR[5], iR[8]), iT[2]);
        float q0 = __fsub_rn(w0, ox), q1 = __fsub_rn(w1, oy), q2 = __fsub_rn(w2, oz);
        float zw = dot3_fma(q0, q1, q2, dwx, dwy, dwz);

        float v = hit ? zw : MISS;

        // 32-bit register bitonic sort of the run (within-run tie order is
        // output-irrelevant: same node/mask, equal values).
        unsigned k = float_to_ord(v);
        #pragma unroll
        for (int kk = 2; kk <= 32; kk <<= 1) {
            #pragma unroll
            for (int j = kk >> 1; j > 0; j >>= 1) {
                unsigned o = __shfl_xor_sync(0xffffffffu, k, j);
                bool low = (lane & j) == 0;
                bool asc = (lane & kk) == 0;
                unsigned mn = k < o ? k : o;
                unsigned mx = k < o ? o : k;
                k = (low == asc) ? mn : mx;
            }
        }
        myord = k;
        gpos = (m << 5) + lane;
        s_objA[gpos] = myord;
    }
    __syncthreads();

    // ---- payload-free merge tree: 32->64->128->256->512 ----
    if (wid >= 2) gpos = merge_round<5>(s_objA, s_objB, gpos, myord);
    __syncthreads();
    if (wid >= 2) gpos = merge_round<6>(s_objB, s_objA, gpos, myord);
    __syncthreads();
    if (wid >= 2) gpos = merge_round<7>(s_objA, s_objB, gpos, myord);
    __syncthreads();
    if (wid >= 2) gpos = merge_round<8>(s_objB, s_objA, gpos, myord);
    __syncthreads();

    // ---- final merge with the base run + packed staging ----
    {
        int fin;
        if (wid >= 2) fin = gpos + cnt_le32<N_BASE>(s_base, myord);
        else          fin = tid  + cnt_lt32<N_ZOBJ>(s_objA, myord);
        s_pack[fin] = ((unsigned long long)myord << 32)
                    | (unsigned)(mynode + 1);
    }
    __syncthreads();

    // ---- coalesced output ----
    {
        unsigned long long pk = s_pack[tid];
        float v = ord_to_float((unsigned)(pk >> 32));
        int nd = (int)(pk & 0xFFu) - 1;
        size_t ob = (size_t)n * TOTAL + tid;
        out_len [ob] = v;
        out_node[ob] = (float)nd;
        out_mask[ob] = (nd >= 0) ? 1.f : 0.f;
    }
}

// ---------------------------------------------------------------------------
extern "C" void kernel_launch(void* const* d_in, const int* in_sizes, int n_in,
                              void* d_out, int out_size) {
    const float* origins    = (const float*)d_in[0];
    const float* directions = (const float*)d_in[1];
    const float* lengths    = (const float*)d_in[2];
    const float* trafos     = (const float*)d_in[3];
    // d_in[4] = rots_w2o unused (composed linear part identical to trafos@scales)
    const float* scales     = (const float*)d_in[5];

    float* out = (float*)d_out;
    size_t nc = (size_t)N_RAYS * TOTAL;
    float* o_len  = out;
    float* o_node = out + nc;
    float* o_mask = out + 2 * nc;
    float* o_pts  = out + 3 * nc;
    float* o_dirs = o_pts + (size_t)N_OBJ * N_RAYS * N_SAMPLES * 3;

    precompute_kernel<<<1, 32>>>(trafos, scales);
    fused_kernel<<<N_RAYS, TOTAL>>>(origins, directions, lengths,
                                    o_len, o_node, o_mask, o_pts, o_dirs);
}

// round 13
// speedup vs baseline: 1.2385x; 1.2385x over previous
#include <cuda_runtime.h>
#include <stdint.h>

#define N_RAYS    32768
#define N_OBJ     16
#define N_SAMPLES 32
#define N_BASE    64
#define N_ZOBJ    (N_OBJ * N_SAMPLES)            // 512
#define TOTAL     (N_BASE + N_ZOBJ)              // 576
#define MISS      1e10f

// ---- per-object transform constants + linspace table ----
__device__ float g_R [N_OBJ][9];
__device__ float g_T [N_OBJ][3];
__device__ float g_iR[N_OBJ][9];
__device__ float g_iT[N_OBJ][3];
__device__ float g_lin[32];

// XLA-GPU lowers x/sqrt(s) -> x * rsqrt(s) with rsqrt.approx.f32.
__device__ __forceinline__ float rsqrt_approx(float x) {
    float r;
    asm("rsqrt.approx.f32 %0, %1;" : "=f"(r) : "f"(x));
    return r;
}

// ---------------------------------------------------------------------------
// Kernel 0: pt_mat = trafos @ scales; inverse exact in fp64, rounded to fp32.
// Also fills the linspace table rn(s/31) (identical bits to in-kernel fdiv).
// ---------------------------------------------------------------------------
__global__ void precompute_kernel(const float* __restrict__ trafos,
                                  const float* __restrict__ scales) {
    int m = threadIdx.x;
    g_lin[m & 31] = __fdiv_rn((float)(m & 31), 31.0f);
    if (m >= N_OBJ) return;
    const float* A = trafos + m * 16;
    const float* B = scales + m * 16;
    float s0 = B[0], s1 = B[5], s2 = B[10];
    float R[9], T[3];
    #pragma unroll
    for (int i = 0; i < 3; i++) {
        R[i * 3 + 0] = __fmul_rn(A[i * 4 + 0], s0);
        R[i * 3 + 1] = __fmul_rn(A[i * 4 + 1], s1);
        R[i * 3 + 2] = __fmul_rn(A[i * 4 + 2], s2);
    }
    T[0] = __fmul_rn(A[12], s0);
    T[1] = __fmul_rn(A[13], s1);
    T[2] = __fmul_rn(A[14], s2);

    double a = R[0], b = R[1], c = R[2];
    double d = R[3], e = R[4], f = R[5];
    double g = R[6], h = R[7], i = R[8];
    double A0 = e * i - f * h, B0 = -(d * i - f * g), C0 = d * h - e * g;
    double D0 = -(b * i - c * h), E0 = a * i - c * g, F0 = -(a * h - b * g);
    double G0 = b * f - c * e, H0 = -(a * f - c * d), I0 = a * e - b * d;
    double det = a * A0 + b * B0 + c * C0;
    double id = 1.0 / det;
    double iR[9] = { A0 * id, D0 * id, G0 * id,
                     B0 * id, E0 * id, H0 * id,
                     C0 * id, F0 * id, I0 * id };
    double iT[3];
    #pragma unroll
    for (int j = 0; j < 3; j++)
        iT[j] = -((double)T[0] * iR[0 + j] + (double)T[1] * iR[3 + j]
                  + (double)T[2] * iR[6 + j]);

    #pragma unroll
    for (int k = 0; k < 9; k++) { g_R[m][k] = R[k]; g_iR[m][k] = (float)iR[k]; }
    #pragma unroll
    for (int k = 0; k < 3; k++) { g_T[m][k] = T[k]; g_iT[m][k] = (float)iT[k]; }
}

__device__ __forceinline__ float dot3_fma(float x0, float x1, float x2,
                                          float m0, float m1, float m2) {
    return fmaf(x2, m2, fmaf(x1, m1, __fmul_rn(x0, m0)));
}

__device__ __forceinline__ unsigned float_to_ord(float f) {
    unsigned u = __float_as_uint(f);
    return (u & 0x80000000u) ? ~u : (u | 0x80000000u);
}
__device__ __forceinline__ float ord_to_float(unsigned u) {
    return (u & 0x80000000u) ? __uint_as_float(u ^ 0x80000000u)
                             : __uint_as_float(~u);
}

// Branchless counts over power-of-two-length sorted arrays (32-bit keys).
template <int L>
__device__ __forceinline__ int cnt_lt32(const unsigned* __restrict__ a, unsigned u) {
    int base = 0;
    #pragma unroll
    for (int half = L >> 1; half > 0; half >>= 1)
        if (a[base + half - 1] < u) base += half;
    return base + ((a[base] < u) ? 1 : 0);
}
template <int L>
__device__ __forceinline__ int cnt_le32(const unsigned* __restrict__ a, unsigned u) {
    int base = 0;
    #pragma unroll
    for (int half = L >> 1; half > 0; half >>= 1)
        if (a[base + half - 1] <= u) base += half;
    return base + ((a[base] <= u) ? 1 : 0);
}

// One merge round: runs of length 2^LOG2H -> 2^(LOG2H+1). Key stays in a
// register; only the 4-byte ord moves through smem. Left run uses cnt_lt of
// right (left's original indices are smaller), right uses cnt_le.
template <int LOG2H>
__device__ __forceinline__ int merge_round(const unsigned* __restrict__ src,
                                           unsigned* __restrict__ dst,
                                           int gpos, unsigned ord) {
    constexpr int HALF = 1 << LOG2H;
    int rank = gpos & (HALF - 1);
    int run  = gpos >> LOG2H;
    const unsigned* other = src + ((run ^ 1) << LOG2H);
    int cnt = (run & 1) ? cnt_le32<HALF>(other, ord)
                        : cnt_lt32<HALF>(other, ord);
    int np = ((run >> 1) << (LOG2H + 1)) + rank + cnt;
    dst[np] = ord;
    return np;
}

// ---------------------------------------------------------------------------
// Fused kernel: one block (576 threads) per ray. R11 flat structure.
// Sort: sorted-run fast path (z is monotone in s up to fp noise; misses are
// constant) with bitonic fallback, then payload-free 32-bit merge tree.
// ---------------------------------------------------------------------------
__global__ void __launch_bounds__(TOTAL, 3)
fused_kernel(const float* __restrict__ origins,
             const float* __restrict__ directions,
             const float* __restrict__ lengths,
             float* __restrict__ out_len,
             float* __restrict__ out_node,
             float* __restrict__ out_mask,
             float* __restrict__ out_pts,
             float* __restrict__ out_dirs) {
    __shared__ unsigned           s_objA[N_ZOBJ];
    __shared__ unsigned           s_objB[N_ZOBJ];
    __shared__ unsigned           s_base[N_BASE];
    __shared__ unsigned long long s_pack[TOTAL];

    const int n    = blockIdx.x;
    const int tid  = threadIdx.x;
    const int wid  = tid >> 5;
    const int lane = tid & 31;

    unsigned myord = 0;
    int gpos = 0;
    int mynode = -1;

    if (wid < 2) {
        // base lengths: pre-sorted ascending; written once, never moved
        float f = __ldg(lengths + (size_t)n * N_BASE + tid);
        myord = float_to_ord(f);
        s_base[tid] = myord;
    } else {
        const int m = wid - 2;

        float ox = __ldg(origins + 3 * n + 0);
        float oy = __ldg(origins + 3 * n + 1);
        float oz = __ldg(origins + 3 * n + 2);
        float dx = __ldg(directions + 3 * n + 0);
        float dy = __ldg(directions + 3 * n + 1);
        float dz = __ldg(directions + 3 * n + 2);

        float dss = __fadd_rn(__fadd_rn(__fmul_rn(dx, dx), __fmul_rn(dy, dy)),
                              __fmul_rn(dz, dz));
        float drs = rsqrt_approx(dss);
        float dwx = __fmul_rn(dx, drs), dwy = __fmul_rn(dy, drs), dwz = __fmul_rn(dz, drs);

        const float* R = g_R[m];
        const float* T = g_T[m];
        float oo0 = __fadd_rn(dot3_fma(ox, oy, oz, R[0], R[3], R[6]), T[0]);
        float oo1 = __fadd_rn(dot3_fma(ox, oy, oz, R[1], R[4], R[7]), T[1]);
        float oo2 = __fadd_rn(dot3_fma(ox, oy, oz, R[2], R[5], R[8]), T[2]);
        float dr0 = dot3_fma(dwx, dwy, dwz, R[0], R[3], R[6]);
        float dr1 = dot3_fma(dwx, dwy, dwz, R[1], R[4], R[7]);
        float dr2 = dot3_fma(dwx, dwy, dwz, R[2], R[5], R[8]);
        float oss = __fadd_rn(__fadd_rn(__fmul_rn(dr0, dr0), __fmul_rn(dr1, dr1)),
                              __fmul_rn(dr2, dr2));
        float ors = rsqrt_approx(oss);
        float do0 = __fmul_rn(dr0, ors), do1 = __fmul_rn(dr1, ors), do2 = __fmul_rn(dr2, ors);

        float i0 = __fdiv_rn(1.f, do0), i1 = __fdiv_rn(1.f, do1), i2 = __fdiv_rn(1.f, do2);
        float t0x = __fmul_rn(__fsub_rn(-1.f, oo0), i0), t1x = __fmul_rn(__fsub_rn(1.f, oo0), i0);
        float t0y = __fmul_rn(__fsub_rn(-1.f, oo1), i1), t1y = __fmul_rn(__fsub_rn(1.f, oo1), i1);
        float t0z = __fmul_rn(__fsub_rn(-1.f, oo2), i2), t1z = __fmul_rn(__fsub_rn(1.f, oo2), i2);
        float tmin = fmaxf(fmaxf(fminf(t0x, t1x), fminf(t0y, t1y)), fminf(t0z, t1z));
        float tmax = fminf(fminf(fmaxf(t0x, t1x), fmaxf(t0y, t1y)), fmaxf(t0z, t1z));
        bool hit = (tmax > tmin) && (tmax > 0.f);
        float tin = fmaxf(tmin, 0.f);
        float hf  = hit ? 1.f : 0.f;
        mynode = hit ? m : -1;

        float lin = __ldg(&g_lin[lane]);   // rn(lane/31), precomputed
        float zo  = __fadd_rn(tin, __fmul_rn(__fsub_rn(tmax, tin), lin));
        float p0 = __fadd_rn(oo0, __fmul_rn(do0, zo));
        float p1 = __fadd_rn(oo1, __fmul_rn(do1, zo));
        float p2 = __fadd_rn(oo2, __fmul_rn(do2, zo));

        size_t base = ((size_t)(m * N_RAYS + n) * N_SAMPLES + lane) * 3;
        out_pts [base + 0] = __fmul_rn(p0, hf);
        out_pts [base + 1] = __fmul_rn(p1, hf);
        out_pts [base + 2] = __fmul_rn(p2, hf);
        out_dirs[base + 0] = __fmul_rn(do0, hf);
        out_dirs[base + 1] = __fmul_rn(do1, hf);
        out_dirs[base + 2] = __fmul_rn(do2, hf);

        const float* iR = g_iR[m];
        const float* iT = g_iT[m];
        float w0 = __fadd_rn(dot3_fma(p0, p1, p2, iR[0], iR[3], iR[6]), iT[0]);
        float w1 = __fadd_rn(dot3_fma(p0, p1, p2, iR[1], iR[4], iR[7]), iT[1]);
        float w2 = __fadd_rn(dot3_fma(p0, p1, p2, iR[2], iR[5], iR[8]), iT[2]);
        float q0 = __fsub_rn(w0, ox), q1 = __fsub_rn(w1, oy), q2 = __fsub_rn(w2, oz);
        float zw = dot3_fma(q0, q1, q2, dwx, dwy, dwz);

        float v = hit ? zw : MISS;

        // Fast path: z is monotone in s for hits (increments >> ulp) and
        // constant (MISS) otherwise — the run is almost always pre-sorted.
        // Within-run tie order is output-irrelevant (same node/mask/value).
        unsigned k = float_to_ord(v);
        unsigned prev = __shfl_up_sync(0xffffffffu, k, 1);
        bool ok = (lane == 0) || (prev <= k);
        if (!__all_sync(0xffffffffu, ok)) {
            #pragma unroll
            for (int kk = 2; kk <= 32; kk <<= 1) {
                #pragma unroll
                for (int j = kk >> 1; j > 0; j >>= 1) {
                    unsigned o = __shfl_xor_sync(0xffffffffu, k, j);
                    bool low = (lane & j) == 0;
                    bool asc = (lane & kk) == 0;
                    unsigned mn = k < o ? k : o;
                    unsigned mx = k < o ? o : k;
                    k = (low == asc) ? mn : mx;
                }
            }
        }
        myord = k;
        gpos = (m << 5) + lane;
        s_objA[gpos] = myord;
    }
    __syncthreads();

    // ---- payload-free merge tree: 32->64->128->256->512 ----
    if (wid >= 2) gpos = merge_round<5>(s_objA, s_objB, gpos, myord);
    __syncthreads();
    if (wid >= 2) gpos = merge_round<6>(s_objB, s_objA, gpos, myord);
    __syncthreads();
    if (wid >= 2) gpos = merge_round<7>(s_objA, s_objB, gpos, myord);
    __syncthreads();
    if (wid >= 2) gpos = merge_round<8>(s_objB, s_objA, gpos, myord);
    __syncthreads();

    // ---- final merge with the base run + packed staging ----
    {
        int fin;
        if (wid >= 2) fin = gpos + cnt_le32<N_BASE>(s_base, myord);
        else          fin = tid  + cnt_lt32<N_ZOBJ>(s_objA, myord);
        s_pack[fin] = ((unsigned long long)myord << 32)
                    | (unsigned)(mynode + 1);
    }
    __syncthreads();

    // ---- coalesced output ----
    {
        unsigned long long pk = s_pack[tid];
        float v = ord_to_float((unsigned)(pk >> 32));
        int nd = (int)(pk & 0xFFu) - 1;
        size_t ob = (size_t)n * TOTAL + tid;
        out_len [ob] = v;
        out_node[ob] = (float)nd;
        out_mask[ob] = (nd >= 0) ? 1.f : 0.f;
    }
}

// ---------------------------------------------------------------------------
extern "C" void kernel_launch(void* const* d_in, const int* in_sizes, int n_in,
                              void* d_out, int out_size) {
    const float* origins    = (const float*)d_in[0];
    const float* directions = (const float*)d_in[1];
    const float* lengths    = (const float*)d_in[2];
    const float* trafos     = (const float*)d_in[3];
    // d_in[4] = rots_w2o unused (composed linear part identical to trafos@scales)
    const float* scales     = (const float*)d_in[5];

    float* out = (float*)d_out;
    size_t nc = (size_t)N_RAYS * TOTAL;
    float* o_len  = out;
    float* o_node = out + nc;
    float* o_mask = out + 2 * nc;
    float* o_pts  = out + 3 * nc;
    float* o_dirs = o_pts + (size_t)N_OBJ * N_RAYS * N_SAMPLES * 3;

    precompute_kernel<<<1, 32>>>(trafos, scales);
    fused_kernel<<<N_RAYS, TOTAL>>>(origins, directions, lengths,
                                    o_len, o_node, o_mask, o_pts, o_dirs);
}

// round 14
// speedup vs baseline: 1.7327x; 1.3991x over previous
#include <cuda_runtime.h>
#include <stdint.h>

#define N_RAYS    32768
#define N_OBJ     16
#define N_SAMPLES 32
#define N_BASE    64
#define N_ZOBJ    (N_OBJ * N_SAMPLES)            // 512
#define TOTAL     (N_BASE + N_ZOBJ)              // 576
#define MISS      1e10f

// ---- per-object transform constants + linspace table ----
__device__ float g_R [N_OBJ][9];
__device__ float g_T [N_OBJ][3];
__device__ float g_iR[N_OBJ][9];
__device__ float g_iT[N_OBJ][3];
__device__ float g_lin[32];

// XLA-GPU lowers x/sqrt(s) -> x * rsqrt(s) with rsqrt.approx.f32.
__device__ __forceinline__ float rsqrt_approx(float x) {
    float r;
    asm("rsqrt.approx.f32 %0, %1;" : "=f"(r) : "f"(x));
    return r;
}

// ---------------------------------------------------------------------------
// Kernel 0: pt_mat = trafos @ scales; inverse exact in fp64, rounded to fp32.
// Also fills the linspace table rn(s/31) (identical bits to in-kernel fdiv).
// ---------------------------------------------------------------------------
__global__ void precompute_kernel(const float* __restrict__ trafos,
                                  const float* __restrict__ scales) {
    int m = threadIdx.x;
    g_lin[m & 31] = __fdiv_rn((float)(m & 31), 31.0f);
    if (m >= N_OBJ) return;
    const float* A = trafos + m * 16;
    const float* B = scales + m * 16;
    float s0 = B[0], s1 = B[5], s2 = B[10];
    float R[9], T[3];
    #pragma unroll
    for (int i = 0; i < 3; i++) {
        R[i * 3 + 0] = __fmul_rn(A[i * 4 + 0], s0);
        R[i * 3 + 1] = __fmul_rn(A[i * 4 + 1], s1);
        R[i * 3 + 2] = __fmul_rn(A[i * 4 + 2], s2);
    }
    T[0] = __fmul_rn(A[12], s0);
    T[1] = __fmul_rn(A[13], s1);
    T[2] = __fmul_rn(A[14], s2);

    double a = R[0], b = R[1], c = R[2];
    double d = R[3], e = R[4], f = R[5];
    double g = R[6], h = R[7], i = R[8];
    double A0 = e * i - f * h, B0 = -(d * i - f * g), C0 = d * h - e * g;
    double D0 = -(b * i - c * h), E0 = a * i - c * g, F0 = -(a * h - b * g);
    double G0 = b * f - c * e, H0 = -(a * f - c * d), I0 = a * e - b * d;
    double det = a * A0 + b * B0 + c * C0;
    double id = 1.0 / det;
    double iR[9] = { A0 * id, D0 * id, G0 * id,
                     B0 * id, E0 * id, H0 * id,
                     C0 * id, F0 * id, I0 * id };
    double iT[3];
    #pragma unroll
    for (int j = 0; j < 3; j++)
        iT[j] = -((double)T[0] * iR[0 + j] + (double)T[1] * iR[3 + j]
                  + (double)T[2] * iR[6 + j]);

    #pragma unroll
    for (int k = 0; k < 9; k++) { g_R[m][k] = R[k]; g_iR[m][k] = (float)iR[k]; }
    #pragma unroll
    for (int k = 0; k < 3; k++) { g_T[m][k] = T[k]; g_iT[m][k] = (float)iT[k]; }
}

__device__ __forceinline__ float dot3_fma(float x0, float x1, float x2,
                                          float m0, float m1, float m2) {
    return fmaf(x2, m2, fmaf(x1, m1, __fmul_rn(x0, m0)));
}

__device__ __forceinline__ unsigned float_to_ord(float f) {
    unsigned u = __float_as_uint(f);
    return (u & 0x80000000u) ? ~u : (u | 0x80000000u);
}
__device__ __forceinline__ float ord_to_float(unsigned u) {
    return (u & 0x80000000u) ? __uint_as_float(u ^ 0x80000000u)
                             : __uint_as_float(~u);
}

// Branchless lower_bound counts. cnt_le(u) == cnt_lt(u+1) (keys < 0xFFFFFFFF).
template <int L>
__device__ __forceinline__ int cnt_lt_fix(const unsigned* __restrict__ a, unsigned u) {
    int base = 0;
    #pragma unroll
    for (int half = L >> 1; half > 0; half >>= 1)
        if (a[base + half - 1] < u) base += half;
    return base + ((a[base] < u) ? 1 : 0);
}
__device__ __forceinline__ int cnt_lt_rt(const unsigned* __restrict__ a, int lg,
                                         unsigned u) {
    int base = 0;
    for (int half = 1 << (lg - 1); half > 0; half >>= 1)
        if (a[base + half - 1] < u) base += half;
    return base + ((a[base] < u) ? 1 : 0);
}

// ---------------------------------------------------------------------------
// Fused kernel: one block (576 threads) per ray.
// Runs are all-real or all-sentinel (hit is warp-uniform). Compact the H hit
// runs, pad to P=pow2(H) sentinel runs, merge only 32P elements in log2(P)
// rounds; remaining miss warps write the provably-sentinel tail directly.
// ---------------------------------------------------------------------------
__global__ void __launch_bounds__(TOTAL, 3)
fused_kernel(const float* __restrict__ origins,
             const float* __restrict__ directions,
             const float* __restrict__ lengths,
             float* __restrict__ out_len,
             float* __restrict__ out_node,
             float* __restrict__ out_mask,
             float* __restrict__ out_pts,
             float* __restrict__ out_dirs) {
    __shared__ unsigned           s_objA[N_ZOBJ];
    __shared__ unsigned           s_objB[N_ZOBJ];
    __shared__ unsigned           s_base[N_BASE];
    __shared__ unsigned long long s_pack[TOTAL];
    __shared__ unsigned           s_mask;

    const int n    = blockIdx.x;
    const int tid  = threadIdx.x;
    const int wid  = tid >> 5;
    const int lane = tid & 31;

    if (tid == 0) s_mask = 0;
    __syncthreads();

    unsigned myord = 0;
    int mynode = -1;

    if (wid < 2) {
        // base lengths: pre-sorted ascending
        float f = __ldg(lengths + (size_t)n * N_BASE + tid);
        myord = float_to_ord(f);
        s_base[tid] = myord;
    } else {
        const int m = wid - 2;

        float ox = __ldg(origins + 3 * n + 0);
        float oy = __ldg(origins + 3 * n + 1);
        float oz = __ldg(origins + 3 * n + 2);
        float dx = __ldg(directions + 3 * n + 0);
        float dy = __ldg(directions + 3 * n + 1);
        float dz = __ldg(directions + 3 * n + 2);

        float dss = __fadd_rn(__fadd_rn(__fmul_rn(dx, dx), __fmul_rn(dy, dy)),
                              __fmul_rn(dz, dz));
        float drs = rsqrt_approx(dss);
        float dwx = __fmul_rn(dx, drs), dwy = __fmul_rn(dy, drs), dwz = __fmul_rn(dz, drs);

        const float* R = g_R[m];
        const float* T = g_T[m];
        float oo0 = __fadd_rn(dot3_fma(ox, oy, oz, R[0], R[3], R[6]), T[0]);
        float oo1 = __fadd_rn(dot3_fma(ox, oy, oz, R[1], R[4], R[7]), T[1]);
        float oo2 = __fadd_rn(dot3_fma(ox, oy, oz, R[2], R[5], R[8]), T[2]);
        float dr0 = dot3_fma(dwx, dwy, dwz, R[0], R[3], R[6]);
        float dr1 = dot3_fma(dwx, dwy, dwz, R[1], R[4], R[7]);
        float dr2 = dot3_fma(dwx, dwy, dwz, R[2], R[5], R[8]);
        float oss = __fadd_rn(__fadd_rn(__fmul_rn(dr0, dr0), __fmul_rn(dr1, dr1)),
                              __fmul_rn(dr2, dr2));
        float ors = rsqrt_approx(oss);
        float do0 = __fmul_rn(dr0, ors), do1 = __fmul_rn(dr1, ors), do2 = __fmul_rn(dr2, ors);

        float i0 = __fdiv_rn(1.f, do0), i1 = __fdiv_rn(1.f, do1), i2 = __fdiv_rn(1.f, do2);
        float t0x = __fmul_rn(__fsub_rn(-1.f, oo0), i0), t1x = __fmul_rn(__fsub_rn(1.f, oo0), i0);
        float t0y = __fmul_rn(__fsub_rn(-1.f, oo1), i1), t1y = __fmul_rn(__fsub_rn(1.f, oo1), i1);
        float t0z = __fmul_rn(__fsub_rn(-1.f, oo2), i2), t1z = __fmul_rn(__fsub_rn(1.f, oo2), i2);
        float tmin = fmaxf(fmaxf(fminf(t0x, t1x), fminf(t0y, t1y)), fminf(t0z, t1z));
        float tmax = fminf(fminf(fmaxf(t0x, t1x), fmaxf(t0y, t1y)), fmaxf(t0z, t1z));
        bool hit = (tmax > tmin) && (tmax > 0.f);
        float tin = fmaxf(tmin, 0.f);
        float hf  = hit ? 1.f : 0.f;
        mynode = hit ? m : -1;

        float lin = __ldg(&g_lin[lane]);   // rn(lane/31)
        float zo  = __fadd_rn(tin, __fmul_rn(__fsub_rn(tmax, tin), lin));
        float p0 = __fadd_rn(oo0, __fmul_rn(do0, zo));
        float p1 = __fadd_rn(oo1, __fmul_rn(do1, zo));
        float p2 = __fadd_rn(oo2, __fmul_rn(do2, zo));

        size_t base = ((size_t)(m * N_RAYS + n) * N_SAMPLES + lane) * 3;
        out_pts [base + 0] = __fmul_rn(p0, hf);
        out_pts [base + 1] = __fmul_rn(p1, hf);
        out_pts [base + 2] = __fmul_rn(p2, hf);
        out_dirs[base + 0] = __fmul_rn(do0, hf);
        out_dirs[base + 1] = __fmul_rn(do1, hf);
        out_dirs[base + 2] = __fmul_rn(do2, hf);

        const float* iR = g_iR[m];
        const float* iT = g_iT[m];
        float w0 = __fadd_rn(dot3_fma(p0, p1, p2, iR[0], iR[3], iR[6]), iT[0]);
        float w1 = __fadd_rn(dot3_fma(p0, p1, p2, iR[1], iR[4], iR[7]), iT[1]);
        float w2 = __fadd_rn(dot3_fma(p0, p1, p2, iR[2], iR[5], iR[8]), iT[2]);
        float q0 = __fsub_rn(w0, ox), q1 = __fsub_rn(w1, oy), q2 = __fsub_rn(w2, oz);
        float zw = dot3_fma(q0, q1, q2, dwx, dwy, dwz);

        float v = hit ? zw : MISS;

        // sorted fast-path (z monotone for hits; constant for misses)
        unsigned k = float_to_ord(v);
        unsigned prev = __shfl_up_sync(0xffffffffu, k, 1);
        bool ok = (lane == 0) || (prev <= k);
        if (!__all_sync(0xffffffffu, ok)) {
            #pragma unroll
            for (int kk = 2; kk <= 32; kk <<= 1) {
                #pragma unroll
                for (int j = kk >> 1; j > 0; j >>= 1) {
                    unsigned o = __shfl_xor_sync(0xffffffffu, k, j);
                    bool low = (lane & j) == 0;
                    bool asc = (lane & kk) == 0;
                    unsigned mn = k < o ? k : o;
                    unsigned mx = k < o ? o : k;
                    k = (low == asc) ? mn : mx;
                }
            }
        }
        myord = k;
        if (lane == 0 && hit) atomicOr(&s_mask, 1u << m);
    }
    __syncthreads();

    // ---- compaction / padding / direct sentinel tail ----
    const unsigned mask = s_mask;
    const int H   = __popc(mask);
    const int lgP = (H <= 1) ? 0 : (32 - __clz(H - 1));
    const int P   = 1 << lgP;

    bool participant = false;
    int gpos = 0;
    if (wid >= 2) {
        const int m = wid - 2;
        if ((mask >> m) & 1u) {
            participant = true;
            gpos = (__popc(mask & ((1u << m) - 1u)) << 5) + lane;
        } else {
            int missrank = __popc(~mask & ((1u << m) - 1u));
            if (missrank < P - H) {
                participant = true;              // padding sentinel run
                gpos = ((H + missrank) << 5) + lane;
            } else {
                // provably-sentinel tail: write outputs directly
                size_t ob = (size_t)n * TOTAL
                          + (N_BASE + (P << 5) + ((missrank - (P - H)) << 5) + lane);
                out_len [ob] = MISS;
                out_node[ob] = -1.f;
                out_mask[ob] = 0.f;
            }
        }
        if (participant) s_objA[gpos] = myord;
    }
    __syncthreads();

    // ---- merge tree over 32P compacted elements (lgP rounds) ----
    unsigned* cur = s_objA;
    unsigned* nxt = s_objB;
    for (int lg = 5; lg < 5 + lgP; lg++) {
        if (participant) {
            int L = 1 << lg;
            int rank = gpos & (L - 1);
            int run  = gpos >> lg;
            const unsigned* other = cur + ((run ^ 1) << lg);
            int cnt = cnt_lt_rt(other, lg, myord + (unsigned)(run & 1));
            gpos = ((run >> 1) << (lg + 1)) + rank + cnt;
            nxt[gpos] = myord;
        }
        __syncthreads();
        unsigned* t = cur; cur = nxt; nxt = t;
    }

    // ---- final merge with the base run + packed staging ----
    if (participant) {
        int fin = gpos + cnt_lt_fix<N_BASE>(s_base, myord + 1u);   // cnt_le
        s_pack[fin] = ((unsigned long long)myord << 32) | (unsigned)(mynode + 1);
    } else if (wid < 2) {
        int fin = tid + cnt_lt_rt(cur, 5 + lgP, myord);
        s_pack[fin] = ((unsigned long long)myord << 32) | 0u;      // node -1
    }
    __syncthreads();

    // ---- coalesced output of the staged region [0, 64+32P) ----
    if (tid < N_BASE + (P << 5)) {
        unsigned long long pk = s_pack[tid];
        float v = ord_to_float((unsigned)(pk >> 32));
        int nd = (int)(pk & 0xFFu) - 1;
        size_t ob = (size_t)n * TOTAL + tid;
        out_len [ob] = v;
        out_node[ob] = (float)nd;
        out_mask[ob] = (nd >= 0) ? 1.f : 0.f;
    }
}

// ---------------------------------------------------------------------------
extern "C" void kernel_launch(void* const* d_in, const int* in_sizes, int n_in,
                              void* d_out, int out_size) {
    const float* origins    = (const float*)d_in[0];
    const float* directions = (const float*)d_in[1];
    const float* lengths    = (const float*)d_in[2];
    const float* trafos     = (const float*)d_in[3];
    // d_in[4] = rots_w2o unused (composed linear part identical to trafos@scales)
    const float* scales     = (const float*)d_in[5];

    float* out = (float*)d_out;
    size_t nc = (size_t)N_RAYS * TOTAL;
    float* o_len  = out;
    float* o_node = out + nc;
    float* o_mask = out + 2 * nc;
    float* o_pts  = out + 3 * nc;
    float* o_dirs = o_pts + (size_t)N_OBJ * N_RAYS * N_SAMPLES * 3;

    precompute_kernel<<<1, 32>>>(trafos, scales);
    fused_kernel<<<N_RAYS, TOTAL>>>(origins, directions, lengths,
                                    o_len, o_node, o_mask, o_pts, o_dirs);
}

// round 15
// speedup vs baseline: 2.0568x; 1.1870x over previous
#include <cuda_runtime.h>
#include <stdint.h>

#define N_RAYS    32768
#define N_OBJ     16
#define N_SAMPLES 32
#define N_BASE    64
#define N_ZOBJ    (N_OBJ * N_SAMPLES)            // 512
#define TOTAL     (N_BASE + N_ZOBJ)              // 576
#define NTHREADS  512
#define MISS      1e10f

// ---- per-object transform constants + linspace table ----
__device__ float g_R [N_OBJ][9];
__device__ float g_T [N_OBJ][3];
__device__ float g_iR[N_OBJ][9];
__device__ float g_iT[N_OBJ][3];
__device__ float g_lin[32];

// XLA-GPU lowers x/sqrt(s) -> x * rsqrt(s) with rsqrt.approx.f32.
__device__ __forceinline__ float rsqrt_approx(float x) {
    float r;
    asm("rsqrt.approx.f32 %0, %1;" : "=f"(r) : "f"(x));
    return r;
}

// ---------------------------------------------------------------------------
// Kernel 0: pt_mat = trafos @ scales; inverse exact in fp64, rounded to fp32.
// Also fills the linspace table rn(s/31) (identical bits to in-kernel fdiv).
// ---------------------------------------------------------------------------
__global__ void precompute_kernel(const float* __restrict__ trafos,
                                  const float* __restrict__ scales) {
    int m = threadIdx.x;
    g_lin[m & 31] = __fdiv_rn((float)(m & 31), 31.0f);
    if (m >= N_OBJ) return;
    const float* A = trafos + m * 16;
    const float* B = scales + m * 16;
    float s0 = B[0], s1 = B[5], s2 = B[10];
    float R[9], T[3];
    #pragma unroll
    for (int i = 0; i < 3; i++) {
        R[i * 3 + 0] = __fmul_rn(A[i * 4 + 0], s0);
        R[i * 3 + 1] = __fmul_rn(A[i * 4 + 1], s1);
        R[i * 3 + 2] = __fmul_rn(A[i * 4 + 2], s2);
    }
    T[0] = __fmul_rn(A[12], s0);
    T[1] = __fmul_rn(A[13], s1);
    T[2] = __fmul_rn(A[14], s2);

    double a = R[0], b = R[1], c = R[2];
    double d = R[3], e = R[4], f = R[5];
    double g = R[6], h = R[7], i = R[8];
    double A0 = e * i - f * h, B0 = -(d * i - f * g), C0 = d * h - e * g;
    double D0 = -(b * i - c * h), E0 = a * i - c * g, F0 = -(a * h - b * g);
    double G0 = b * f - c * e, H0 = -(a * f - c * d), I0 = a * e - b * d;
    double det = a * A0 + b * B0 + c * C0;
    double id = 1.0 / det;
    double iR[9] = { A0 * id, D0 * id, G0 * id,
                     B0 * id, E0 * id, H0 * id,
                     C0 * id, F0 * id, I0 * id };
    double iT[3];
    #pragma unroll
    for (int j = 0; j < 3; j++)
        iT[j] = -((double)T[0] * iR[0 + j] + (double)T[1] * iR[3 + j]
                  + (double)T[2] * iR[6 + j]);

    #pragma unroll
    for (int k = 0; k < 9; k++) { g_R[m][k] = R[k]; g_iR[m][k] = (float)iR[k]; }
    #pragma unroll
    for (int k = 0; k < 3; k++) { g_T[m][k] = T[k]; g_iT[m][k] = (float)iT[k]; }
}

__device__ __forceinline__ float dot3_fma(float x0, float x1, float x2,
                                          float m0, float m1, float m2) {
    return fmaf(x2, m2, fmaf(x1, m1, __fmul_rn(x0, m0)));
}

__device__ __forceinline__ unsigned float_to_ord(float f) {
    unsigned u = __float_as_uint(f);
    return (u & 0x80000000u) ? ~u : (u | 0x80000000u);
}
__device__ __forceinline__ float ord_to_float(unsigned u) {
    return (u & 0x80000000u) ? __uint_as_float(u ^ 0x80000000u)
                             : __uint_as_float(~u);
}

// Branchless lower_bound counts. cnt_le(u) == cnt_lt(u+1) (keys < 0xFFFFFFFF).
template <int L>
__device__ __forceinline__ int cnt_lt_fix(const unsigned* __restrict__ a, unsigned u) {
    int base = 0;
    #pragma unroll
    for (int half = L >> 1; half > 0; half >>= 1)
        if (a[base + half - 1] < u) base += half;
    return base + ((a[base] < u) ? 1 : 0);
}
__device__ __forceinline__ int cnt_lt_rt(const unsigned* __restrict__ a, int lg,
                                         unsigned u) {
    int base = 0;
    for (int half = 1 << (lg - 1); half > 0; half >>= 1)
        if (a[base + half - 1] < u) base += half;
    return base + ((a[base] < u) ? 1 : 0);
}

// ---------------------------------------------------------------------------
// Fused kernel: one block (512 threads = 16 object warps) per ray.
// Threads 0-63 additionally carry the base run (load + final search).
// Hit runs compacted, padded to P=pow2(H); merge tree has log2(P) rounds;
// the provably-sentinel tail is written directly by miss warps.
// ---------------------------------------------------------------------------
__global__ void __launch_bounds__(NTHREADS, 4)
fused_kernel(const float* __restrict__ origins,
             const float* __restrict__ directions,
             const float* __restrict__ lengths,
             float* __restrict__ out_len,
             float* __restrict__ out_node,
             float* __restrict__ out_mask,
             float* __restrict__ out_pts,
             float* __restrict__ out_dirs) {
    __shared__ unsigned           s_objA[N_ZOBJ];
    __shared__ unsigned           s_objB[N_ZOBJ];
    __shared__ unsigned           s_base[N_BASE];
    __shared__ unsigned long long s_pack[TOTAL];
    __shared__ unsigned           s_maskv;

    const int n    = blockIdx.x;
    const int tid  = threadIdx.x;
    const int m    = tid >> 5;          // object = warp id
    const int lane = tid & 31;

    if (tid == 0) s_maskv = 0;

    // base run: threads 0-63 double-duty
    unsigned bord = 0;
    if (tid < N_BASE) {
        float f = __ldg(lengths + (size_t)n * N_BASE + tid);
        bord = float_to_ord(f);
        s_base[tid] = bord;
    }

    // ---- per-object geometry (all 16 warps) ----
    float ox = __ldg(origins + 3 * n + 0);
    float oy = __ldg(origins + 3 * n + 1);
    float oz = __ldg(origins + 3 * n + 2);
    float dx = __ldg(directions + 3 * n + 0);
    float dy = __ldg(directions + 3 * n + 1);
    float dz = __ldg(directions + 3 * n + 2);

    float dss = __fadd_rn(__fadd_rn(__fmul_rn(dx, dx), __fmul_rn(dy, dy)),
                          __fmul_rn(dz, dz));
    float drs = rsqrt_approx(dss);
    float dwx = __fmul_rn(dx, drs), dwy = __fmul_rn(dy, drs), dwz = __fmul_rn(dz, drs);

    const float* R = g_R[m];
    const float* T = g_T[m];
    float oo0 = __fadd_rn(dot3_fma(ox, oy, oz, R[0], R[3], R[6]), T[0]);
    float oo1 = __fadd_rn(dot3_fma(ox, oy, oz, R[1], R[4], R[7]), T[1]);
    float oo2 = __fadd_rn(dot3_fma(ox, oy, oz, R[2], R[5], R[8]), T[2]);
    float dr0 = dot3_fma(dwx, dwy, dwz, R[0], R[3], R[6]);
    float dr1 = dot3_fma(dwx, dwy, dwz, R[1], R[4], R[7]);
    float dr2 = dot3_fma(dwx, dwy, dwz, R[2], R[5], R[8]);
    float oss = __fadd_rn(__fadd_rn(__fmul_rn(dr0, dr0), __fmul_rn(dr1, dr1)),
                          __fmul_rn(dr2, dr2));
    float ors = rsqrt_approx(oss);
    float do0 = __fmul_rn(dr0, ors), do1 = __fmul_rn(dr1, ors), do2 = __fmul_rn(dr2, ors);

    float i0 = __fdiv_rn(1.f, do0), i1 = __fdiv_rn(1.f, do1), i2 = __fdiv_rn(1.f, do2);
    float t0x = __fmul_rn(__fsub_rn(-1.f, oo0), i0), t1x = __fmul_rn(__fsub_rn(1.f, oo0), i0);
    float t0y = __fmul_rn(__fsub_rn(-1.f, oo1), i1), t1y = __fmul_rn(__fsub_rn(1.f, oo1), i1);
    float t0z = __fmul_rn(__fsub_rn(-1.f, oo2), i2), t1z = __fmul_rn(__fsub_rn(1.f, oo2), i2);
    float tmin = fmaxf(fmaxf(fminf(t0x, t1x), fminf(t0y, t1y)), fminf(t0z, t1z));
    float tmax = fminf(fminf(fmaxf(t0x, t1x), fmaxf(t0y, t1y)), fmaxf(t0z, t1z));
    bool hit = (tmax > tmin) && (tmax > 0.f);
    float tin = fmaxf(tmin, 0.f);
    float hf  = hit ? 1.f : 0.f;
    int mynode = hit ? m : -1;

    float lin = __ldg(&g_lin[lane]);   // rn(lane/31)
    float zo  = __fadd_rn(tin, __fmul_rn(__fsub_rn(tmax, tin), lin));
    float p0 = __fadd_rn(oo0, __fmul_rn(do0, zo));
    float p1 = __fadd_rn(oo1, __fmul_rn(do1, zo));
    float p2 = __fadd_rn(oo2, __fmul_rn(do2, zo));

    size_t pbase = ((size_t)(m * N_RAYS + n) * N_SAMPLES + lane) * 3;
    out_pts [pbase + 0] = __fmul_rn(p0, hf);
    out_pts [pbase + 1] = __fmul_rn(p1, hf);
    out_pts [pbase + 2] = __fmul_rn(p2, hf);
    out_dirs[pbase + 0] = __fmul_rn(do0, hf);
    out_dirs[pbase + 1] = __fmul_rn(do1, hf);
    out_dirs[pbase + 2] = __fmul_rn(do2, hf);

    const float* iR = g_iR[m];
    const float* iT = g_iT[m];
    float w0 = __fadd_rn(dot3_fma(p0, p1, p2, iR[0], iR[3], iR[6]), iT[0]);
    float w1 = __fadd_rn(dot3_fma(p0, p1, p2, iR[1], iR[4], iR[7]), iT[1]);
    float w2 = __fadd_rn(dot3_fma(p0, p1, p2, iR[2], iR[5], iR[8]), iT[2]);
    float q0 = __fsub_rn(w0, ox), q1 = __fsub_rn(w1, oy), q2 = __fsub_rn(w2, oz);
    float zw = dot3_fma(q0, q1, q2, dwx, dwy, dwz);

    float v = hit ? zw : MISS;

    // sorted fast-path (z monotone for hits; constant for misses)
    unsigned myord = float_to_ord(v);
    {
        unsigned prev = __shfl_up_sync(0xffffffffu, myord, 1);
        bool ok = (lane == 0) || (prev <= myord);
        if (!__all_sync(0xffffffffu, ok)) {
            unsigned k = myord;
            #pragma unroll
            for (int kk = 2; kk <= 32; kk <<= 1) {
                #pragma unroll
                for (int j = kk >> 1; j > 0; j >>= 1) {
                    unsigned o = __shfl_xor_sync(0xffffffffu, k, j);
                    bool low = (lane & j) == 0;
                    bool asc = (lane & kk) == 0;
                    unsigned mn = k < o ? k : o;
                    unsigned mx = k < o ? o : k;
                    k = (low == asc) ? mn : mx;
                }
            }
            myord = k;
        }
    }
    if (lane == 0 && hit) atomicOr(&s_maskv, 1u << m);
    __syncthreads();

    // ---- compaction / padding / direct sentinel tail ----
    const unsigned mask = s_maskv;
    const int H   = __popc(mask);
    const int lgP = (H <= 1) ? 0 : (32 - __clz(H - 1));
    const int P   = 1 << lgP;

    bool participant = false;
    int gpos = 0;
    if ((mask >> m) & 1u) {
        participant = true;
        gpos = (__popc(mask & ((1u << m) - 1u)) << 5) + lane;
    } else {
        int missrank = __popc(~mask & ((1u << m) - 1u));
        if (missrank < P - H) {
            participant = true;              // padding sentinel run
            gpos = ((H + missrank) << 5) + lane;
        } else {
            // provably-sentinel tail: write outputs directly
            size_t ob = (size_t)n * TOTAL
                      + (N_BASE + (P << 5) + ((missrank - (P - H)) << 5) + lane);
            out_len [ob] = MISS;
            out_node[ob] = -1.f;
            out_mask[ob] = 0.f;
        }
    }
    if (participant) s_objA[gpos] = myord;
    __syncthreads();

    // ---- merge tree over 32P compacted elements (lgP rounds) ----
    unsigned* cur = s_objA;
    unsigned* nxt = s_objB;
    for (int lg = 5; lg < 5 + lgP; lg++) {
        if (participant) {
            int L = 1 << lg;
            int rank = gpos & (L - 1);
            int run  = gpos >> lg;
            const unsigned* other = cur + ((run ^ 1) << lg);
            int cnt = cnt_lt_rt(other, lg, myord + (unsigned)(run & 1));
            gpos = ((run >> 1) << (lg + 1)) + rank + cnt;
            nxt[gpos] = myord;
        }
        __syncthreads();
        unsigned* t = cur; cur = nxt; nxt = t;
    }

    // ---- final merge with the base run + packed staging ----
    if (participant) {
        int fin = gpos + cnt_lt_fix<N_BASE>(s_base, myord + 1u);   // cnt_le
        s_pack[fin] = ((unsigned long long)myord << 32) | (unsigned)(mynode + 1);
    }
    if (tid < N_BASE) {
        int fin = tid + cnt_lt_rt(cur, 5 + lgP, bord);
        s_pack[fin] = ((unsigned long long)bord << 32) | 0u;       // node -1
    }
    __syncthreads();

    // ---- coalesced output of the staged region [0, 64+32P) ----
    const int staged = N_BASE + (P << 5);
    for (int i = tid; i < staged; i += NTHREADS) {
        unsigned long long pk = s_pack[i];
        float vv = ord_to_float((unsigned)(pk >> 32));
        int nd = (int)(pk & 0xFFu) - 1;
        size_t ob = (size_t)n * TOTAL + i;
        out_len [ob] = vv;
        out_node[ob] = (float)nd;
        out_mask[ob] = (nd >= 0) ? 1.f : 0.f;
    }
}

// ---------------------------------------------------------------------------
extern "C" void kernel_launch(void* const* d_in, const int* in_sizes, int n_in,
                              void* d_out, int out_size) {
    const float* origins    = (const float*)d_in[0];
    const float* directions = (const float*)d_in[1];
    const float* lengths    = (const float*)d_in[2];
    const float* trafos     = (const float*)d_in[3];
    // d_in[4] = rots_w2o unused (composed linear part identical to trafos@scales)
    const float* scales     = (const float*)d_in[5];

    float* out = (float*)d_out;
    size_t nc = (size_t)N_RAYS * TOTAL;
    float* o_len  = out;
    float* o_node = out + nc;
    float* o_mask = out + 2 * nc;
    float* o_pts  = out + 3 * nc;
    float* o_dirs = o_pts + (size_t)N_OBJ * N_RAYS * N_SAMPLES * 3;

    precompute_kernel<<<1, 32>>>(trafos, scales);
    fused_kernel<<<N_RAYS, NTHREADS>>>(origins, directions, lengths,
                                       o_len, o_node, o_mask, o_pts, o_dirs);
}

// round 16
// speedup vs baseline: 2.1037x; 1.0228x over previous
#include <cuda_runtime.h>
#include <stdint.h>

#define N_RAYS    32768
#define N_OBJ     16
#define N_SAMPLES 32
#define N_BASE    64
#define N_ZOBJ    (N_OBJ * N_SAMPLES)            // 512
#define TOTAL     (N_BASE + N_ZOBJ)              // 576
#define NTHREADS  512
#define MISS      1e10f

// ---- per-object transform constants + linspace table ----
__device__ float g_R [N_OBJ][9];
__device__ float g_T [N_OBJ][3];
__device__ float g_iR[N_OBJ][9];
__device__ float g_iT[N_OBJ][3];
__device__ float g_lin[32];

// XLA-GPU lowers x/sqrt(s) -> x * rsqrt(s) with rsqrt.approx.f32.
__device__ __forceinline__ float rsqrt_approx(float x) {
    float r;
    asm("rsqrt.approx.f32 %0, %1;" : "=f"(r) : "f"(x));
    return r;
}

// ---------------------------------------------------------------------------
// Kernel 0: pt_mat = trafos @ scales; inverse exact in fp64, rounded to fp32.
// Also fills the linspace table rn(s/31) (identical bits to in-kernel fdiv).
// ---------------------------------------------------------------------------
__global__ void precompute_kernel(const float* __restrict__ trafos,
                                  const float* __restrict__ scales) {
    int m = threadIdx.x;
    g_lin[m & 31] = __fdiv_rn((float)(m & 31), 31.0f);
    if (m >= N_OBJ) return;
    const float* A = trafos + m * 16;
    const float* B = scales + m * 16;
    float s0 = B[0], s1 = B[5], s2 = B[10];
    float R[9], T[3];
    #pragma unroll
    for (int i = 0; i < 3; i++) {
        R[i * 3 + 0] = __fmul_rn(A[i * 4 + 0], s0);
        R[i * 3 + 1] = __fmul_rn(A[i * 4 + 1], s1);
        R[i * 3 + 2] = __fmul_rn(A[i * 4 + 2], s2);
    }
    T[0] = __fmul_rn(A[12], s0);
    T[1] = __fmul_rn(A[13], s1);
    T[2] = __fmul_rn(A[14], s2);

    double a = R[0], b = R[1], c = R[2];
    double d = R[3], e = R[4], f = R[5];
    double g = R[6], h = R[7], i = R[8];
    double A0 = e * i - f * h, B0 = -(d * i - f * g), C0 = d * h - e * g;
    double D0 = -(b * i - c * h), E0 = a * i - c * g, F0 = -(a * h - b * g);
    double G0 = b * f - c * e, H0 = -(a * f - c * d), I0 = a * e - b * d;
    double det = a * A0 + b * B0 + c * C0;
    double id = 1.0 / det;
    double iR[9] = { A0 * id, D0 * id, G0 * id,
                     B0 * id, E0 * id, H0 * id,
                     C0 * id, F0 * id, I0 * id };
    double iT[3];
    #pragma unroll
    for (int j = 0; j < 3; j++)
        iT[j] = -((double)T[0] * iR[0 + j] + (double)T[1] * iR[3 + j]
                  + (double)T[2] * iR[6 + j]);

    #pragma unroll
    for (int k = 0; k < 9; k++) { g_R[m][k] = R[k]; g_iR[m][k] = (float)iR[k]; }
    #pragma unroll
    for (int k = 0; k < 3; k++) { g_T[m][k] = T[k]; g_iT[m][k] = (float)iT[k]; }
}

__device__ __forceinline__ float dot3_fma(float x0, float x1, float x2,
                                          float m0, float m1, float m2) {
    return fmaf(x2, m2, fmaf(x1, m1, __fmul_rn(x0, m0)));
}

__device__ __forceinline__ unsigned float_to_ord(float f) {
    unsigned u = __float_as_uint(f);
    return (u & 0x80000000u) ? ~u : (u | 0x80000000u);
}
__device__ __forceinline__ float ord_to_float(unsigned u) {
    return (u & 0x80000000u) ? __uint_as_float(u ^ 0x80000000u)
                             : __uint_as_float(~u);
}

// Branchless lower_bound count, fully unrolled. cnt_le(u) == cnt_lt(u+1).
template <int L>
__device__ __forceinline__ int cnt_lt_fix(const unsigned* __restrict__ a, unsigned u) {
    int base = 0;
    #pragma unroll
    for (int half = L >> 1; half > 0; half >>= 1)
        if (a[base + half - 1] < u) base += half;
    return base + ((a[base] < u) ? 1 : 0);
}

// One statically-sized merge round: src runs of length 2^LG -> dst 2^(LG+1).
template <int LG>
__device__ __forceinline__ int merge_fix(const unsigned* __restrict__ src,
                                         unsigned* __restrict__ dst,
                                         int gpos, unsigned ord) {
    constexpr int L = 1 << LG;
    int rank = gpos & (L - 1);
    int run  = gpos >> LG;
    const unsigned* other = src + ((run ^ 1) << LG);
    int cnt = cnt_lt_fix<L>(other, ord + (unsigned)(run & 1));  // lt / le
    int np = ((run >> 1) << (LG + 1)) + rank + cnt;
    dst[np] = ord;
    return np;
}

// ---------------------------------------------------------------------------
// Fused kernel: one block (512 threads = 16 object warps) per ray.
// Threads 0-63 double-duty the base run. Hit runs compacted to P=pow2(H);
// statically-unrolled merge rounds; sentinel tail written directly.
// ---------------------------------------------------------------------------
__global__ void __launch_bounds__(NTHREADS, 4)
fused_kernel(const float* __restrict__ origins,
             const float* __restrict__ directions,
             const float* __restrict__ lengths,
             float* __restrict__ out_len,
             float* __restrict__ out_node,
             float* __restrict__ out_mask,
             float* __restrict__ out_pts,
             float* __restrict__ out_dirs) {
    __shared__ unsigned           s_objA[N_ZOBJ];
    __shared__ unsigned           s_objB[N_ZOBJ];
    __shared__ unsigned           s_base[N_BASE];
    __shared__ unsigned long long s_pack[TOTAL];
    __shared__ unsigned           s_maskv;

    const int n    = blockIdx.x;
    const int tid  = threadIdx.x;
    const int m    = tid >> 5;          // object = warp id
    const int lane = tid & 31;

    if (tid == 0) s_maskv = 0;

    // base run: threads 0-63 double-duty
    unsigned bord = 0;
    if (tid < N_BASE) {
        float f = __ldg(lengths + (unsigned)(n * N_BASE + tid));
        bord = float_to_ord(f);
        s_base[tid] = bord;
    }

    // ---- per-object geometry ----
    float ox = __ldg(origins + 3u * n + 0);
    float oy = __ldg(origins + 3u * n + 1);
    float oz = __ldg(origins + 3u * n + 2);
    float dx = __ldg(directions + 3u * n + 0);
    float dy = __ldg(directions + 3u * n + 1);
    float dz = __ldg(directions + 3u * n + 2);

    float dss = __fadd_rn(__fadd_rn(__fmul_rn(dx, dx), __fmul_rn(dy, dy)),
                          __fmul_rn(dz, dz));
    float drs = rsqrt_approx(dss);
    float dwx = __fmul_rn(dx, drs), dwy = __fmul_rn(dy, drs), dwz = __fmul_rn(dz, drs);

    const float* R = g_R[m];
    const float* T = g_T[m];
    float oo0 = __fadd_rn(dot3_fma(ox, oy, oz, R[0], R[3], R[6]), T[0]);
    float oo1 = __fadd_rn(dot3_fma(ox, oy, oz, R[1], R[4], R[7]), T[1]);
    float oo2 = __fadd_rn(dot3_fma(ox, oy, oz, R[2], R[5], R[8]), T[2]);
    float dr0 = dot3_fma(dwx, dwy, dwz, R[0], R[3], R[6]);
    float dr1 = dot3_fma(dwx, dwy, dwz, R[1], R[4], R[7]);
    float dr2 = dot3_fma(dwx, dwy, dwz, R[2], R[5], R[8]);
    float oss = __fadd_rn(__fadd_rn(__fmul_rn(dr0, dr0), __fmul_rn(dr1, dr1)),
                          __fmul_rn(dr2, dr2));
    float ors = rsqrt_approx(oss);
    float do0 = __fmul_rn(dr0, ors), do1 = __fmul_rn(dr1, ors), do2 = __fmul_rn(dr2, ors);

    float i0 = __fdiv_rn(1.f, do0), i1 = __fdiv_rn(1.f, do1), i2 = __fdiv_rn(1.f, do2);
    float t0x = __fmul_rn(__fsub_rn(-1.f, oo0), i0), t1x = __fmul_rn(__fsub_rn(1.f, oo0), i0);
    float t0y = __fmul_rn(__fsub_rn(-1.f, oo1), i1), t1y = __fmul_rn(__fsub_rn(1.f, oo1), i1);
    float t0z = __fmul_rn(__fsub_rn(-1.f, oo2), i2), t1z = __fmul_rn(__fsub_rn(1.f, oo2), i2);
    float tmin = fmaxf(fmaxf(fminf(t0x, t1x), fminf(t0y, t1y)), fminf(t0z, t1z));
    float tmax = fminf(fminf(fmaxf(t0x, t1x), fmaxf(t0y, t1y)), fmaxf(t0z, t1z));
    bool hit = (tmax > tmin) && (tmax > 0.f);
    float tin = fmaxf(tmin, 0.f);
    float hf  = hit ? 1.f : 0.f;
    int mynode = hit ? m : -1;

    float lin = __ldg(&g_lin[lane]);   // rn(lane/31)
    float zo  = __fadd_rn(tin, __fmul_rn(__fsub_rn(tmax, tin), lin));
    float p0 = __fadd_rn(oo0, __fmul_rn(do0, zo));
    float p1 = __fadd_rn(oo1, __fmul_rn(do1, zo));
    float p2 = __fadd_rn(oo2, __fmul_rn(do2, zo));

    unsigned pbase = ((unsigned)(m * N_RAYS + n) * N_SAMPLES + (unsigned)lane) * 3u;
    out_pts [pbase + 0] = __fmul_rn(p0, hf);
    out_pts [pbase + 1] = __fmul_rn(p1, hf);
    out_pts [pbase + 2] = __fmul_rn(p2, hf);
    out_dirs[pbase + 0] = __fmul_rn(do0, hf);
    out_dirs[pbase + 1] = __fmul_rn(do1, hf);
    out_dirs[pbase + 2] = __fmul_rn(do2, hf);

    // world-z only matters for hits (miss -> MISS sentinel); hit is
    // warp-uniform so this branch is divergence-free.
    unsigned myord;
    if (hit) {
        const float* iR = g_iR[m];
        const float* iT = g_iT[m];
        float w0 = __fadd_rn(dot3_fma(p0, p1, p2, iR[0], iR[3], iR[6]), iT[0]);
        float w1 = __fadd_rn(dot3_fma(p0, p1, p2, iR[1], iR[4], iR[7]), iT[1]);
        float w2 = __fadd_rn(dot3_fma(p0, p1, p2, iR[2], iR[5], iR[8]), iT[2]);
        float q0 = __fsub_rn(w0, ox), q1 = __fsub_rn(w1, oy), q2 = __fsub_rn(w2, oz);
        float zw = dot3_fma(q0, q1, q2, dwx, dwy, dwz);

        myord = float_to_ord(zw);
        // sorted fast-path (z monotone in s up to fp noise)
        unsigned prev = __shfl_up_sync(0xffffffffu, myord, 1);
        bool ok = (lane == 0) || (prev <= myord);
        if (!__all_sync(0xffffffffu, ok)) {
            unsigned k = myord;
            #pragma unroll
            for (int kk = 2; kk <= 32; kk <<= 1) {
                #pragma unroll
                for (int j = kk >> 1; j > 0; j >>= 1) {
                    unsigned o = __shfl_xor_sync(0xffffffffu, k, j);
                    bool low = (lane & j) == 0;
                    bool asc = (lane & kk) == 0;
                    unsigned mn = k < o ? k : o;
                    unsigned mx = k < o ? o : k;
                    k = (low == asc) ? mn : mx;
                }
            }
            myord = k;
        }
        if (lane == 0) atomicOr(&s_maskv, 1u << m);
    } else {
        myord = float_to_ord(MISS);   // compile-time constant
    }
    __syncthreads();

    // ---- compaction / padding / direct sentinel tail ----
    const unsigned mask = s_maskv;
    const int H   = __popc(mask);
    const int lgP = (H <= 1) ? 0 : (32 - __clz(H - 1));
    const int P   = 1 << lgP;

    bool participant = false;
    int gpos = 0;
    if ((mask >> m) & 1u) {
        participant = true;
        gpos = (__popc(mask & ((1u << m) - 1u)) << 5) + lane;
    } else {
        int missrank = __popc(~mask & ((1u << m) - 1u));
        if (missrank < P - H) {
            participant = true;              // padding sentinel run
            gpos = ((H + missrank) << 5) + lane;
        } else {
            // provably-sentinel tail: write outputs directly
            unsigned ob = (unsigned)n * TOTAL
                        + (unsigned)(N_BASE + (P << 5)
                                     + ((missrank - (P - H)) << 5) + lane);
            out_len [ob] = MISS;
            out_node[ob] = -1.f;
            out_mask[ob] = 0.f;
        }
    }
    if (participant) s_objA[gpos] = myord;
    __syncthreads();

    // ---- statically-unrolled merge rounds (block-uniform guards) ----
    if (lgP >= 1) {
        if (participant) gpos = merge_fix<5>(s_objA, s_objB, gpos, myord);
        __syncthreads();
    }
    if (lgP >= 2) {
        if (participant) gpos = merge_fix<6>(s_objB, s_objA, gpos, myord);
        __syncthreads();
    }
    if (lgP >= 3) {
        if (participant) gpos = merge_fix<7>(s_objA, s_objB, gpos, myord);
        __syncthreads();
    }
    if (lgP >= 4) {
        if (participant) gpos = merge_fix<8>(s_objB, s_objA, gpos, myord);
        __syncthreads();
    }
    // final object array: lgP even -> A, odd -> B
    const unsigned* fobj = (lgP & 1) ? s_objB : s_objA;

    // ---- final merge with the base run + packed staging ----
    if (participant) {
        int fin = gpos + cnt_lt_fix<N_BASE>(s_base, myord + 1u);   // cnt_le
        s_pack[fin] = ((unsigned long long)myord << 32) | (unsigned)(mynode + 1);
    }
    if (tid < N_BASE) {
        int c;
        switch (lgP) {
            case 0:  c = cnt_lt_fix<32 >(fobj, bord); break;
            case 1:  c = cnt_lt_fix<64 >(fobj, bord); break;
            case 2:  c = cnt_lt_fix<128>(fobj, bord); break;
            case 3:  c = cnt_lt_fix<256>(fobj, bord); break;
            default: c = cnt_lt_fix<512>(fobj, bord); break;
        }
        s_pack[tid + c] = ((unsigned long long)bord << 32) | 0u;   // node -1
    }
    __syncthreads();

    // ---- coalesced output of the staged region [0, 64+32P) ----
    const int staged = N_BASE + (P << 5);
    const unsigned rayoff = (unsigned)n * TOTAL;
    for (int i = tid; i < staged; i += NTHREADS) {
        unsigned long long pk = s_pack[i];
        float vv = ord_to_float((unsigned)(pk >> 32));
        int nd = (int)(pk & 0xFFu) - 1;
        unsigned ob = rayoff + (unsigned)i;
        out_len [ob] = vv;
        out_node[ob] = (float)nd;
        out_mask[ob] = (nd >= 0) ? 1.f : 0.f;
    }
}

// ---------------------------------------------------------------------------
extern "C" void kernel_launch(void* const* d_in, const int* in_sizes, int n_in,
                              void* d_out, int out_size) {
    const float* origins    = (const float*)d_in[0];
    const float* directions = (const float*)d_in[1];
    const float* lengths    = (const float*)d_in[2];
    const float* trafos     = (const float*)d_in[3];
    // d_in[4] = rots_w2o unused (composed linear part identical to trafos@scales)
    const float* scales     = (const float*)d_in[5];

    float* out = (float*)d_out;
    size_t nc = (size_t)N_RAYS * TOTAL;
    float* o_len  = out;
    float* o_node = out + nc;
    float* o_mask = out + 2 * nc;
    float* o_pts  = out + 3 * nc;
    float* o_dirs = o_pts + (size_t)N_OBJ * N_RAYS * N_SAMPLES * 3;

    precompute_kernel<<<1, 32>>>(trafos, scales);
    fused_kernel<<<N_RAYS, NTHREADS>>>(origins, directions, lengths,
                                       o_len, o_node, o_mask, o_pts, o_dirs);
}

// round 17
// speedup vs baseline: 2.2837x; 1.0855x over previous
#include <cuda_runtime.h>
#include <stdint.h>

#define N_RAYS    32768
#define N_OBJ     16
#define N_SAMPLES 32
#define N_BASE    64
#define N_ZOBJ    (N_OBJ * N_SAMPLES)            // 512
#define TOTAL     (N_BASE + N_ZOBJ)              // 576
#define NTHREADS  512
#define MISS      1e10f

// ---- per-object transform constants + linspace table ----
__device__ float g_R [N_OBJ][9];
__device__ float g_T [N_OBJ][3];
__device__ float g_iR[N_OBJ][9];
__device__ float g_iT[N_OBJ][3];
__device__ float g_lin[32];

// XLA-GPU lowers x/sqrt(s) -> x * rsqrt(s) with rsqrt.approx.f32.
__device__ __forceinline__ float rsqrt_approx(float x) {
    float r;
    asm("rsqrt.approx.f32 %0, %1;" : "=f"(r) : "f"(x));
    return r;
}

// ---------------------------------------------------------------------------
// Kernel 0: pt_mat = trafos @ scales; inverse exact in fp64, rounded to fp32.
// Also fills the linspace table rn(s/31) (identical bits to in-kernel fdiv).
// ---------------------------------------------------------------------------
__global__ void precompute_kernel(const float* __restrict__ trafos,
                                  const float* __restrict__ scales) {
    int m = threadIdx.x;
    g_lin[m & 31] = __fdiv_rn((float)(m & 31), 31.0f);
    if (m >= N_OBJ) return;
    const float* A = trafos + m * 16;
    const float* B = scales + m * 16;
    float s0 = B[0], s1 = B[5], s2 = B[10];
    float R[9], T[3];
    #pragma unroll
    for (int i = 0; i < 3; i++) {
        R[i * 3 + 0] = __fmul_rn(A[i * 4 + 0], s0);
        R[i * 3 + 1] = __fmul_rn(A[i * 4 + 1], s1);
        R[i * 3 + 2] = __fmul_rn(A[i * 4 + 2], s2);
    }
    T[0] = __fmul_rn(A[12], s0);
    T[1] = __fmul_rn(A[13], s1);
    T[2] = __fmul_rn(A[14], s2);

    double a = R[0], b = R[1], c = R[2];
    double d = R[3], e = R[4], f = R[5];
    double g = R[6], h = R[7], i = R[8];
    double A0 = e * i - f * h, B0 = -(d * i - f * g), C0 = d * h - e * g;
    double D0 = -(b * i - c * h), E0 = a * i - c * g, F0 = -(a * h - b * g);
    double G0 = b * f - c * e, H0 = -(a * f - c * d), I0 = a * e - b * d;
    double det = a * A0 + b * B0 + c * C0;
    double id = 1.0 / det;
    double iR[9] = { A0 * id, D0 * id, G0 * id,
                     B0 * id, E0 * id, H0 * id,
                     C0 * id, F0 * id, I0 * id };
    double iT[3];
    #pragma unroll
    for (int j = 0; j < 3; j++)
        iT[j] = -((double)T[0] * iR[0 + j] + (double)T[1] * iR[3 + j]
                  + (double)T[2] * iR[6 + j]);

    #pragma unroll
    for (int k = 0; k < 9; k++) { g_R[m][k] = R[k]; g_iR[m][k] = (float)iR[k]; }
    #pragma unroll
    for (int k = 0; k < 3; k++) { g_T[m][k] = T[k]; g_iT[m][k] = (float)iT[k]; }
}

__device__ __forceinline__ float dot3_fma(float x0, float x1, float x2,
                                          float m0, float m1, float m2) {
    return fmaf(x2, m2, fmaf(x1, m1, __fmul_rn(x0, m0)));
}

__device__ __forceinline__ unsigned float_to_ord(float f) {
    unsigned u = __float_as_uint(f);
    return (u & 0x80000000u) ? ~u : (u | 0x80000000u);
}
__device__ __forceinline__ float ord_to_float(unsigned u) {
    return (u & 0x80000000u) ? __uint_as_float(u ^ 0x80000000u)
                             : __uint_as_float(~u);
}

// Branchless lower_bound count, fully unrolled. cnt_le(u) == cnt_lt(u+1).
template <int L>
__device__ __forceinline__ int cnt_lt_fix(const unsigned* __restrict__ a, unsigned u) {
    int base = 0;
    #pragma unroll
    for (int half = L >> 1; half > 0; half >>= 1)
        if (a[base + half - 1] < u) base += half;
    return base + ((a[base] < u) ? 1 : 0);
}

// One statically-sized merge round: src runs of length 2^LG -> dst 2^(LG+1).
template <int LG>
__device__ __forceinline__ int merge_fix(const unsigned* __restrict__ src,
                                         unsigned* __restrict__ dst,
                                         int gpos, unsigned ord) {
    constexpr int L = 1 << LG;
    int rank = gpos & (L - 1);
    int run  = gpos >> LG;
    const unsigned* other = src + ((run ^ 1) << LG);
    int cnt = cnt_lt_fix<L>(other, ord + (unsigned)(run & 1));  // lt / le
    int np = ((run >> 1) << (LG + 1)) + rank + cnt;
    dst[np] = ord;
    return np;
}

// ---------------------------------------------------------------------------
// Fused kernel: one block (512 threads = 16 object warps) per ray.
// pts/dirs exit via per-warp smem staging + STG.128 (coalesced 384B chunks).
// Threads 0-63 double-duty the base run. Hit runs compacted to P=pow2(H);
// statically-unrolled merge rounds; sentinel tail written directly.
// ---------------------------------------------------------------------------
__global__ void __launch_bounds__(NTHREADS, 4)
fused_kernel(const float* __restrict__ origins,
             const float* __restrict__ directions,
             const float* __restrict__ lengths,
             float* __restrict__ out_len,
             float* __restrict__ out_node,
             float* __restrict__ out_mask,
             float* __restrict__ out_pts,
             float* __restrict__ out_dirs) {
    __shared__ unsigned           s_objA[N_ZOBJ];
    __shared__ unsigned           s_objB[N_ZOBJ];
    __shared__ unsigned           s_base[N_BASE];
    __shared__ unsigned long long s_pack[TOTAL];
    __shared__ float              s_st  [N_OBJ][96];   // per-warp store staging
    __shared__ unsigned           s_maskv;

    const int n    = blockIdx.x;
    const int tid  = threadIdx.x;
    const int m    = tid >> 5;          // object = warp id
    const int lane = tid & 31;

    if (tid == 0) s_maskv = 0;

    // base run: threads 0-63 double-duty
    unsigned bord = 0;
    if (tid < N_BASE) {
        float f = __ldg(lengths + (unsigned)(n * N_BASE + tid));
        bord = float_to_ord(f);
        s_base[tid] = bord;
    }

    // ---- per-object geometry ----
    float ox = __ldg(origins + 3u * n + 0);
    float oy = __ldg(origins + 3u * n + 1);
    float oz = __ldg(origins + 3u * n + 2);
    float dx = __ldg(directions + 3u * n + 0);
    float dy = __ldg(directions + 3u * n + 1);
    float dz = __ldg(directions + 3u * n + 2);

    float dss = __fadd_rn(__fadd_rn(__fmul_rn(dx, dx), __fmul_rn(dy, dy)),
                          __fmul_rn(dz, dz));
    float drs = rsqrt_approx(dss);
    float dwx = __fmul_rn(dx, drs), dwy = __fmul_rn(dy, drs), dwz = __fmul_rn(dz, drs);

    const float* R = g_R[m];
    const float* T = g_T[m];
    float oo0 = __fadd_rn(dot3_fma(ox, oy, oz, R[0], R[3], R[6]), T[0]);
    float oo1 = __fadd_rn(dot3_fma(ox, oy, oz, R[1], R[4], R[7]), T[1]);
    float oo2 = __fadd_rn(dot3_fma(ox, oy, oz, R[2], R[5], R[8]), T[2]);
    float dr0 = dot3_fma(dwx, dwy, dwz, R[0], R[3], R[6]);
    float dr1 = dot3_fma(dwx, dwy, dwz, R[1], R[4], R[7]);
    float dr2 = dot3_fma(dwx, dwy, dwz, R[2], R[5], R[8]);
    float oss = __fadd_rn(__fadd_rn(__fmul_rn(dr0, dr0), __fmul_rn(dr1, dr1)),
                          __fmul_rn(dr2, dr2));
    float ors = rsqrt_approx(oss);
    float do0 = __fmul_rn(dr0, ors), do1 = __fmul_rn(dr1, ors), do2 = __fmul_rn(dr2, ors);

    float i0 = __fdiv_rn(1.f, do0), i1 = __fdiv_rn(1.f, do1), i2 = __fdiv_rn(1.f, do2);
    float t0x = __fmul_rn(__fsub_rn(-1.f, oo0), i0), t1x = __fmul_rn(__fsub_rn(1.f, oo0), i0);
    float t0y = __fmul_rn(__fsub_rn(-1.f, oo1), i1), t1y = __fmul_rn(__fsub_rn(1.f, oo1), i1);
    float t0z = __fmul_rn(__fsub_rn(-1.f, oo2), i2), t1z = __fmul_rn(__fsub_rn(1.f, oo2), i2);
    float tmin = fmaxf(fmaxf(fminf(t0x, t1x), fminf(t0y, t1y)), fminf(t0z, t1z));
    float tmax = fminf(fminf(fmaxf(t0x, t1x), fmaxf(t0y, t1y)), fmaxf(t0z, t1z));
    bool hit = (tmax > tmin) && (tmax > 0.f);
    float tin = fmaxf(tmin, 0.f);
    float hf  = hit ? 1.f : 0.f;
    int mynode = hit ? m : -1;

    float lin = __ldg(&g_lin[lane]);   // rn(lane/31)
    float zo  = __fadd_rn(tin, __fmul_rn(__fsub_rn(tmax, tin), lin));
    float p0 = __fadd_rn(oo0, __fmul_rn(do0, zo));
    float p1 = __fadd_rn(oo1, __fmul_rn(do1, zo));
    float p2 = __fadd_rn(oo2, __fmul_rn(do2, zo));

    // ---- pts/dirs: per-warp smem staging -> coalesced STG.128 ----
    const unsigned chunk = (unsigned)(m * N_RAYS + n) * 96u;   // floats
    {
        float* row = s_st[m];
        row[lane * 3 + 0] = __fmul_rn(p0, hf);
        row[lane * 3 + 1] = __fmul_rn(p1, hf);
        row[lane * 3 + 2] = __fmul_rn(p2, hf);
        __syncwarp();
        if (lane < 24)
            *reinterpret_cast<float4*>(out_pts + chunk + lane * 4u) =
                *reinterpret_cast<const float4*>(row + lane * 4);
        __syncwarp();
        row[lane * 3 + 0] = __fmul_rn(do0, hf);
        row[lane * 3 + 1] = __fmul_rn(do1, hf);
        row[lane * 3 + 2] = __fmul_rn(do2, hf);
        __syncwarp();
        if (lane < 24)
            *reinterpret_cast<float4*>(out_dirs + chunk + lane * 4u) =
                *reinterpret_cast<const float4*>(row + lane * 4);
    }

    // world-z only matters for hits (miss -> MISS sentinel); hit is
    // warp-uniform so this branch is divergence-free.
    unsigned myord;
    if (hit) {
        const float* iR = g_iR[m];
        const float* iT = g_iT[m];
        float w0 = __fadd_rn(dot3_fma(p0, p1, p2, iR[0], iR[3], iR[6]), iT[0]);
        float w1 = __fadd_rn(dot3_fma(p0, p1, p2, iR[1], iR[4], iR[7]), iT[1]);
        float w2 = __fadd_rn(dot3_fma(p0, p1, p2, iR[2], iR[5], iR[8]), iT[2]);
        float q0 = __fsub_rn(w0, ox), q1 = __fsub_rn(w1, oy), q2 = __fsub_rn(w2, oz);
        float zw = dot3_fma(q0, q1, q2, dwx, dwy, dwz);

        myord = float_to_ord(zw);
        // sorted fast-path (z monotone in s up to fp noise)
        unsigned prev = __shfl_up_sync(0xffffffffu, myord, 1);
        bool ok = (lane == 0) || (prev <= myord);
        if (!__all_sync(0xffffffffu, ok)) {
            unsigned k = myord;
            #pragma unroll
            for (int kk = 2; kk <= 32; kk <<= 1) {
                #pragma unroll
                for (int j = kk >> 1; j > 0; j >>= 1) {
                    unsigned o = __shfl_xor_sync(0xffffffffu, k, j);
                    bool low = (lane & j) == 0;
                    bool asc = (lane & kk) == 0;
                    unsigned mn = k < o ? k : o;
                    unsigned mx = k < o ? o : k;
                    k = (low == asc) ? mn : mx;
                }
            }
            myord = k;
        }
        if (lane == 0) atomicOr(&s_maskv, 1u << m);
    } else {
        myord = float_to_ord(MISS);   // compile-time constant
    }
    __syncthreads();

    // ---- compaction / padding / direct sentinel tail ----
    const unsigned mask = s_maskv;
    const int H   = __popc(mask);
    const int lgP = (H <= 1) ? 0 : (32 - __clz(H - 1));
    const int P   = 1 << lgP;

    bool participant = false;
    int gpos = 0;
    if ((mask >> m) & 1u) {
        participant = true;
        gpos = (__popc(mask & ((1u << m) - 1u)) << 5) + lane;
    } else {
        int missrank = __popc(~mask & ((1u << m) - 1u));
        if (missrank < P - H) {
            participant = true;              // padding sentinel run
            gpos = ((H + missrank) << 5) + lane;
        } else {
            // provably-sentinel tail: write outputs directly
            unsigned ob = (unsigned)n * TOTAL
                        + (unsigned)(N_BASE + (P << 5)
                                     + ((missrank - (P - H)) << 5) + lane);
            out_len [ob] = MISS;
            out_node[ob] = -1.f;
            out_mask[ob] = 0.f;
        }
    }
    if (participant) s_objA[gpos] = myord;
    __syncthreads();

    // ---- statically-unrolled merge rounds (block-uniform guards) ----
    if (lgP >= 1) {
        if (participant) gpos = merge_fix<5>(s_objA, s_objB, gpos, myord);
        __syncthreads();
    }
    if (lgP >= 2) {
        if (participant) gpos = merge_fix<6>(s_objB, s_objA, gpos, myord);
        __syncthreads();
    }
    if (lgP >= 3) {
        if (participant) gpos = merge_fix<7>(s_objA, s_objB, gpos, myord);
        __syncthreads();
    }
    if (lgP >= 4) {
        if (participant) gpos = merge_fix<8>(s_objB, s_objA, gpos, myord);
        __syncthreads();
    }
    // final object array: lgP even -> A, odd -> B
    const unsigned* fobj = (lgP & 1) ? s_objB : s_objA;

    // ---- final merge with the base run + packed staging ----
    if (participant) {
        int fin = gpos + cnt_lt_fix<N_BASE>(s_base, myord + 1u);   // cnt_le
        s_pack[fin] = ((unsigned long long)myord << 32) | (unsigned)(mynode + 1);
    }
    if (tid < N_BASE) {
        int c;
        switch (lgP) {
            case 0:  c = cnt_lt_fix<32 >(fobj, bord); break;
            case 1:  c = cnt_lt_fix<64 >(fobj, bord); break;
            case 2:  c = cnt_lt_fix<128>(fobj, bord); break;
            case 3:  c = cnt_lt_fix<256>(fobj, bord); break;
            default: c = cnt_lt_fix<512>(fobj, bord); break;
        }
        s_pack[tid + c] = ((unsigned long long)bord << 32) | 0u;   // node -1
    }
    __syncthreads();

    // ---- coalesced output of the staged region [0, 64+32P) ----
    const int staged = N_BASE + (P << 5);
    const unsigned rayoff = (unsigned)n * TOTAL;
    for (int i = tid; i < staged; i += NTHREADS) {
        unsigned long long pk = s_pack[i];
        float vv = ord_to_float((unsigned)(pk >> 32));
        int nd = (int)(pk & 0xFFu) - 1;
        unsigned ob = rayoff + (unsigned)i;
        out_len [ob] = vv;
        out_node[ob] = (float)nd;
        out_mask[ob] = (nd >= 0) ? 1.f : 0.f;
    }
}

// ---------------------------------------------------------------------------
extern "C" void kernel_launch(void* const* d_in, const int* in_sizes, int n_in,
                              void* d_out, int out_size) {
    const float* origins    = (const float*)d_in[0];
    const float* directions = (const float*)d_in[1];
    const float* lengths    = (const float*)d_in[2];
    const float* trafos     = (const float*)d_in[3];
    // d_in[4] = rots_w2o unused (composed linear part identical to trafos@scales)
    const float* scales     = (const float*)d_in[5];

    float* out = (float*)d_out;
    size_t nc = (size_t)N_RAYS * TOTAL;
    float* o_len  = out;
    float* o_node = out + nc;
    float* o_mask = out + 2 * nc;
    float* o_pts  = out + 3 * nc;
    float* o_dirs = o_pts + (size_t)N_OBJ * N_RAYS * N_SAMPLES * 3;

    precompute_kernel<<<1, 32>>>(trafos, scales);
    fused_kernel<<<N_RAYS, NTHREADS>>>(origins, directions, lengths,
                                       o_len, o_node, o_mask, o_pts, o_dirs);
}